// round 15
// baseline (speedup 1.0000x reference)
#include <cuda_runtime.h>
#include <math.h>
#include <stdint.h>

#define NN 25000
#define EE 400000
#define TOTE (EE + NN)
#define HD 384
#define DH 128

typedef unsigned long long ull;

// ---------------- device scratch ----------------
__device__ __align__(16) float g_xl[NN * HD];
__device__ __align__(16) float g_xr[NN * HD];
__device__ __align__(16) float g_xin[NN * HD];
__device__ __align__(16) float g_h2[NN * HD];
__device__ __align__(16) float g_h[NN * DH];
__device__ __align__(16) float g_y[NN * DH];
__device__ int   g_deg[NN];
__device__ int   g_rowptr[NN + 1];
__device__ int   g_fill[NN];
__device__ int   g_srcs[TOTE];
__device__ float g_bnsum[DH];
__device__ float g_bnsq[DH];

// ---------------- f32x2 helpers ----------------
__device__ __forceinline__ ull dup2(float v) {
    ull d;
    uint32_t u = __float_as_uint(v);
    asm("mov.b64 %0, {%1, %1};" : "=l"(d) : "r"(u));
    return d;
}
__device__ __forceinline__ void unpack2(ull v, float& lo, float& hi) {
    uint32_t a, b;
    asm("mov.b64 {%0, %1}, %2;" : "=r"(a), "=r"(b) : "l"(v));
    lo = __uint_as_float(a);
    hi = __uint_as_float(b);
}
__device__ __forceinline__ void fma2(ull& acc, ull a, ull b) {
    asm("fma.rn.f32x2 %0, %1, %2, %0;" : "+l"(acc) : "l"(a), "l"(b));
}

// ---------------- small helpers ----------------
__device__ __forceinline__ float4 f4add(float4 a, float4 b) {
    return make_float4(a.x + b.x, a.y + b.y, a.z + b.z, a.w + b.w);
}
__device__ __forceinline__ float4 f4scale(float4 a, float s) {
    return make_float4(a.x * s, a.y * s, a.z * s, a.w * s);
}
__device__ __forceinline__ float4 f4fma(float4 a, float s, float4 c) {
    return make_float4(fmaf(a.x, s, c.x), fmaf(a.y, s, c.y),
                       fmaf(a.z, s, c.z), fmaf(a.w, s, c.w));
}
__device__ __forceinline__ float4 f4lrelu(float4 v) {
    const float ns = 0.2f;
    return make_float4(v.x > 0.f ? v.x : ns * v.x,
                       v.y > 0.f ? v.y : ns * v.y,
                       v.z > 0.f ? v.z : ns * v.z,
                       v.w > 0.f ? v.w : ns * v.w);
}
__device__ __forceinline__ float f4dot(float4 a, float4 b) {
    return fmaf(a.x, b.x, fmaf(a.y, b.y, fmaf(a.z, b.z, a.w * b.w)));
}

// ---------------- CSR build ----------------
__global__ void set_int_kernel(int* p, int n, int v) {
    int i = blockIdx.x * blockDim.x + threadIdx.x;
    if (i < n) p[i] = v;
}

__global__ void hist_kernel(const int* __restrict__ ei, int* __restrict__ deg) {
    int i = blockIdx.x * blockDim.x + threadIdx.x;
    if (i < EE) {
        int d = ei[EE + i];
        if (d >= 0 && d < NN) atomicAdd(&deg[d], 1);
    }
}

__global__ void scan_kernel(const int* __restrict__ deg, int* __restrict__ rowptr,
                            int* __restrict__ fill) {
    __shared__ int sh[1024];
    const int CH = 25;
    int t = threadIdx.x;
    int start = t * CH;
    int end = start + CH;
    if (start > NN) start = NN;
    if (end > NN) end = NN;
    int s = 0;
    for (int i = start; i < end; i++) s += deg[i];
    sh[t] = s;
    __syncthreads();
    for (int o = 1; o < 1024; o <<= 1) {
        int v = (t >= o) ? sh[t - o] : 0;
        __syncthreads();
        sh[t] += v;
        __syncthreads();
    }
    int off = (t == 0) ? 0 : sh[t - 1];
    for (int i = start; i < end; i++) {
        rowptr[i] = off;
        fill[i] = off;
        off += deg[i];
    }
    if (t == 1023) rowptr[NN] = sh[1023];
}

__global__ void scatter_kernel(const int* __restrict__ ei, int* __restrict__ fill,
                               int* __restrict__ srcs) {
    int i = blockIdx.x * blockDim.x + threadIdx.x;
    if (i >= TOTE) return;
    int s, d;
    if (i < EE) {
        s = ei[i];
        d = ei[EE + i];
    } else {
        s = d = i - EE;
    }
    if (s < 0 || s >= NN || d < 0 || d >= NN) return;
    int pos = atomicAdd(&fill[d], 1);
    srcs[pos] = s;
}

// ---------------- packed-f32x2 GEMM, double-buffered + swizzled A store ----------------
// (R13 kernel + optional fused BN-stats epilogue: when bnsum != nullptr, each
// CTA accumulates per-column sum/sumsq of its final output tile via smem
// reduction + 2 global atomics per column.)
__global__ void __launch_bounds__(256, 3) gemm_f32x2_kernel(
    const float* __restrict__ A0, const float* __restrict__ A1, int lda0, int lda1,
    int Ksplit, const float* __restrict__ B0, const float* __restrict__ B1, int ldb0,
    int ldb1, int Nsplit, const float* __restrict__ biasA, const float* __restrict__ biasB,
    float* __restrict__ C0, float* __restrict__ C1, int ldc0, int ldc1, int M, int N,
    int K, float* __restrict__ bnsum, float* __restrict__ bnsq) {
    __shared__ float As[2][16][128];
    __shared__ float Bs[2][16][64];

    int tid = threadIdx.x;
    int lane = tid & 31;
    int warp = tid >> 5;
    int ln = lane & 7;
    int lm = lane >> 3;
    int wm = warp >> 1;
    int wn = warp & 1;
    int mb = wm * 32 + lm * 8;
    int nb = wn * 32 + ln * 4;
    int bm = blockIdx.y * 128;
    int bn = blockIdx.x * 64;

    int ar = tid >> 2;
    int akq = (tid & 3) << 2;
    int sw = (akq >> 2) << 3;
    int arx = ar ^ sw;
    int br = tid >> 4;
    int bnc = (tid & 15) << 2;
    int agrow0 = bm + ar;
    int agrow1 = bm + ar + 64;
    int bcol = bn + bnc;

    ull acc[8][2];
#pragma unroll
    for (int i = 0; i < 8; i++) {
        acc[i][0] = 0ull;
        acc[i][1] = 0ull;
    }

    int nchunks = K >> 4;

    float4 va0, va1, vb;
    {
        int kg = akq;
        va0 = make_float4(0.f, 0.f, 0.f, 0.f);
        va1 = va0;
        if (agrow0 < M)
            va0 = (kg < Ksplit) ? *(const float4*)(A0 + (size_t)agrow0 * lda0 + kg)
                                : *(const float4*)(A1 + (size_t)agrow0 * lda1 + (kg - Ksplit));
        if (agrow1 < M)
            va1 = (kg < Ksplit) ? *(const float4*)(A0 + (size_t)agrow1 * lda0 + kg)
                                : *(const float4*)(A1 + (size_t)agrow1 * lda1 + (kg - Ksplit));
        int kgb = br;
        vb = (bcol < Nsplit) ? *(const float4*)(B0 + (size_t)kgb * ldb0 + bcol)
                             : *(const float4*)(B1 + (size_t)kgb * ldb1 + (bcol - Nsplit));
    }
    As[0][akq + 0][arx] = va0.x;
    As[0][akq + 1][arx] = va0.y;
    As[0][akq + 2][arx] = va0.z;
    As[0][akq + 3][arx] = va0.w;
    As[0][akq + 0][arx + 64] = va1.x;
    As[0][akq + 1][arx + 64] = va1.y;
    As[0][akq + 2][arx + 64] = va1.z;
    As[0][akq + 3][arx + 64] = va1.w;
    *(float4*)&Bs[0][br][bnc] = vb;
    __syncthreads();

    for (int kc = 0; kc < nchunks; kc++) {
        int p = kc & 1;
        bool more = (kc + 1) < nchunks;
        if (more) {
            int kg = (kc + 1) * 16 + akq;
            va0 = make_float4(0.f, 0.f, 0.f, 0.f);
            va1 = va0;
            if (agrow0 < M)
                va0 = (kg < Ksplit)
                          ? *(const float4*)(A0 + (size_t)agrow0 * lda0 + kg)
                          : *(const float4*)(A1 + (size_t)agrow0 * lda1 + (kg - Ksplit));
            if (agrow1 < M)
                va1 = (kg < Ksplit)
                          ? *(const float4*)(A0 + (size_t)agrow1 * lda0 + kg)
                          : *(const float4*)(A1 + (size_t)agrow1 * lda1 + (kg - Ksplit));
            int kgb = (kc + 1) * 16 + br;
            vb = (bcol < Nsplit)
                     ? *(const float4*)(B0 + (size_t)kgb * ldb0 + bcol)
                     : *(const float4*)(B1 + (size_t)kgb * ldb1 + (bcol - Nsplit));
        }
#pragma unroll
        for (int kk = 0; kk < 16; kk++) {
            int g = (kk >> 2) << 3;
            int mbx = mb ^ g;
            float4 av0 = *(const float4*)&As[p][kk][mbx];
            float4 av1 = *(const float4*)&As[p][kk][mbx + 4];
            ulonglong2 bq = *(const ulonglong2*)&Bs[p][kk][nb];
            ull ad[8] = {dup2(av0.x), dup2(av0.y), dup2(av0.z), dup2(av0.w),
                         dup2(av1.x), dup2(av1.y), dup2(av1.z), dup2(av1.w)};
#pragma unroll
            for (int i = 0; i < 8; i++) {
                fma2(acc[i][0], ad[i], bq.x);
                fma2(acc[i][1], ad[i], bq.y);
            }
        }
        if (more) {
            int q = p ^ 1;
            As[q][akq + 0][arx] = va0.x;
            As[q][akq + 1][arx] = va0.y;
            As[q][akq + 2][arx] = va0.z;
            As[q][akq + 3][arx] = va0.w;
            As[q][akq + 0][arx + 64] = va1.x;
            As[q][akq + 1][arx + 64] = va1.y;
            As[q][akq + 2][arx + 64] = va1.z;
            As[q][akq + 3][arx + 64] = va1.w;
            *(float4*)&Bs[q][br][bnc] = vb;
            __syncthreads();
        }
    }

    int colg = bn + nb;
    bool side1 = colg >= Nsplit;
    int col = side1 ? colg - Nsplit : colg;
    float* __restrict__ Cp = side1 ? C1 : C0;
    int ldc = side1 ? ldc1 : ldc0;
    const float* __restrict__ bp = side1 ? biasB : biasA;
    float b0 = bp[col], b1v = bp[col + 1], b2v = bp[col + 2], b3v = bp[col + 3];
    float cs0 = 0.f, cs1 = 0.f, cs2 = 0.f, cs3 = 0.f;
    float cq0 = 0.f, cq1 = 0.f, cq2 = 0.f, cq3 = 0.f;
#pragma unroll
    for (int i = 0; i < 8; i++) {
        int row = bm + mb + i;
        if (row >= M) continue;
        float v0, v1, v2, v3;
        unpack2(acc[i][0], v0, v1);
        unpack2(acc[i][1], v2, v3);
        v0 += b0; v1 += b1v; v2 += b2v; v3 += b3v;
        *(float4*)(Cp + (size_t)row * ldc + col) = make_float4(v0, v1, v2, v3);
        cs0 += v0; cs1 += v1; cs2 += v2; cs3 += v3;
        cq0 = fmaf(v0, v0, cq0);
        cq1 = fmaf(v1, v1, cq1);
        cq2 = fmaf(v2, v2, cq2);
        cq3 = fmaf(v3, v3, cq3);
    }

    if (bnsum) {
        // reuse As as a 128-float reduction buffer (sum[64], sq[64])
        __syncthreads();
        float* sred = &As[0][0][0];
        if (tid < 128) sred[tid] = 0.f;
        __syncthreads();
        atomicAdd(&sred[nb + 0], cs0);
        atomicAdd(&sred[nb + 1], cs1);
        atomicAdd(&sred[nb + 2], cs2);
        atomicAdd(&sred[nb + 3], cs3);
        atomicAdd(&sred[64 + nb + 0], cq0);
        atomicAdd(&sred[64 + nb + 1], cq1);
        atomicAdd(&sred[64 + nb + 2], cq2);
        atomicAdd(&sred[64 + nb + 3], cq3);
        __syncthreads();
        if (tid < 64) {
            atomicAdd(&bnsum[bn + tid], sred[tid]);
            atomicAdd(&bnsq[bn + tid], sred[64 + tid]);
        }
    }
}

// ---------------- GATv2 attention: warp per dst, online softmax, 1-edge prefetch ----------------
__global__ void attn_kernel(const float* __restrict__ xl, const float* __restrict__ xr,
                            const float* __restrict__ att, const float* __restrict__ bias,
                            const int* __restrict__ rowptr, const int* __restrict__ srcs,
                            float* __restrict__ out) {
    int w = (blockIdx.x * blockDim.x + threadIdx.x) >> 5;
    if (w >= NN) return;
    int lane = threadIdx.x & 31;
    const float4* xl4 = (const float4*)xl;
    const float4* xr4 = (const float4*)xr;
    const float4* at4 = (const float4*)att;
    const float4* b4 = (const float4*)bias;

    size_t rb = (size_t)w * 96 + lane;
    float4 r0 = xr4[rb], r1 = xr4[rb + 32], r2 = xr4[rb + 64];
    float4 a0 = at4[lane], a1 = at4[32 + lane], a2 = at4[64 + lane];

    float4 acc0 = make_float4(0, 0, 0, 0), acc1 = acc0, acc2 = acc0;
    float den0 = 0.f, den1 = 0.f, den2 = 0.f;
    float m0 = -1e30f, m1 = -1e30f, m2 = -1e30f;

    int beg = rowptr[w], end = rowptr[w + 1];
    // prefetch edge 0 (every node has >= 1 edge: the self loop)
    float4 x0p, x1p, x2p;
    {
        const float4* p = xl4 + (size_t)srcs[beg] * 96 + lane;
        x0p = p[0];
        x1p = p[32];
        x2p = p[64];
    }
    for (int e = beg; e < end; e++) {
        float4 x0 = x0p, x1 = x1p, x2 = x2p;
        if (e + 1 < end) {
            const float4* p = xl4 + (size_t)srcs[e + 1] * 96 + lane;
            x0p = p[0];
            x1p = p[32];
            x2p = p[64];
        }
        float s0 = f4dot(a0, f4lrelu(f4add(x0, r0)));
        float s1 = f4dot(a1, f4lrelu(f4add(x1, r1)));
        float s2 = f4dot(a2, f4lrelu(f4add(x2, r2)));
#pragma unroll
        for (int o = 16; o; o >>= 1) {
            s0 += __shfl_xor_sync(0xffffffffu, s0, o);
            s1 += __shfl_xor_sync(0xffffffffu, s1, o);
            s2 += __shfl_xor_sync(0xffffffffu, s2, o);
        }
        if (s0 > m0) { float cc = __expf(m0 - s0); acc0 = f4scale(acc0, cc); den0 *= cc; m0 = s0; }
        if (s1 > m1) { float cc = __expf(m1 - s1); acc1 = f4scale(acc1, cc); den1 *= cc; m1 = s1; }
        if (s2 > m2) { float cc = __expf(m2 - s2); acc2 = f4scale(acc2, cc); den2 *= cc; m2 = s2; }
        float w0 = __expf(s0 - m0);
        float w1 = __expf(s1 - m1);
        float w2 = __expf(s2 - m2);
        acc0 = f4fma(x0, w0, acc0); den0 += w0;
        acc1 = f4fma(x1, w1, acc1); den1 += w1;
        acc2 = f4fma(x2, w2, acc2); den2 += w2;
    }
    float4* o4 = (float4*)out;
    o4[rb]      = f4add(f4scale(acc0, 1.0f / den0), b4[lane]);
    o4[rb + 32] = f4add(f4scale(acc1, 1.0f / den1), b4[32 + lane]);
    o4[rb + 64] = f4add(f4scale(acc2, 1.0f / den2), b4[64 + lane]);
}

// ---------------- BatchNorm ----------------
__global__ void bn_zero_kernel(float* s, float* q) {
    int i = threadIdx.x;
    if (i < DH) s[i] = 0.f;
    else if (i < 2 * DH) q[i - DH] = 0.f;
}

__global__ void bn_apply_kernel(const float* __restrict__ x, const float* __restrict__ sum,
                                const float* __restrict__ sq, const float* __restrict__ g,
                                const float* __restrict__ be, float* __restrict__ out) {
    int i = blockIdx.x * blockDim.x + threadIdx.x;
    if (i >= NN * DH) return;
    int col = i & (DH - 1);
    const float invN = 1.0f / (float)NN;
    float mu = sum[col] * invN;
    float var = sq[col] * invN - mu * mu;
    float v = g[col] * (x[i] - mu) * rsqrtf(var + 1e-5f) + be[col];
    out[i] = v > 0.f ? v : 0.f;
}

// ---------------- host ----------------
static void* symaddr(const void* sym) {
    void* p = nullptr;
    cudaGetSymbolAddress(&p, sym);
    return p;
}

extern "C" void kernel_launch(void* const* d_in, const int* in_sizes, int n_in,
                              void* d_out, int out_size) {
    const float* x       = (const float*)d_in[0];
    const int* ei        = (const int*)d_in[1];
    const float* Wl1 = (const float*)d_in[2];
    const float* bl1 = (const float*)d_in[3];
    const float* Wr1 = (const float*)d_in[4];
    const float* br1 = (const float*)d_in[5];
    const float* att1 = (const float*)d_in[6];
    const float* bc1 = (const float*)d_in[7];
    const float* g1 = (const float*)d_in[8];
    const float* be1 = (const float*)d_in[9];
    const float* Wl2 = (const float*)d_in[10];
    const float* bl2 = (const float*)d_in[11];
    const float* Wr2 = (const float*)d_in[12];
    const float* br2 = (const float*)d_in[13];
    const float* att2 = (const float*)d_in[14];
    const float* bc2 = (const float*)d_in[15];
    const float* g2 = (const float*)d_in[16];
    const float* be2 = (const float*)d_in[17];
    const float* W1 = (const float*)d_in[18];
    const float* b1 = (const float*)d_in[19];
    const float* W2 = (const float*)d_in[20];
    const float* b2 = (const float*)d_in[21];
    float* out = (float*)d_out;

    float* xl    = (float*)symaddr(g_xl);
    float* xr    = (float*)symaddr(g_xr);
    float* xin   = (float*)symaddr(g_xin);
    float* h2    = (float*)symaddr(g_h2);
    float* h     = (float*)symaddr(g_h);
    float* y     = (float*)symaddr(g_y);
    int* deg     = (int*)symaddr(g_deg);
    int* rowptr  = (int*)symaddr(g_rowptr);
    int* fill    = (int*)symaddr(g_fill);
    int* srcs    = (int*)symaddr(g_srcs);
    float* bnsum = (float*)symaddr(g_bnsum);
    float* bnsq  = (float*)symaddr(g_bnsq);

    const int MT = (NN + 127) / 128;  // 196
    dim3 gN768(2 * HD / 64, MT);      // 12 x 196
    dim3 gN128(DH / 64, MT);          // 2 x 196
    int attn_blocks = (NN * 32 + 255) / 256;

    // CSR part 1 (3 launches so the big fused GEMM sits in the profiled slot)
    set_int_kernel<<<(NN + 255) / 256, 256>>>(deg, NN, 1);
    hist_kernel<<<(EE + 255) / 256, 256>>>(ei, deg);
    scan_kernel<<<1, 1024>>>(deg, rowptr, fill);

    // ---- Layer 1: [xl | xr] = x @ [Wl1 | Wr1] + [bl1 | br1] ----
    gemm_f32x2_kernel<<<gN768, 256>>>(x, x, DH, DH, DH, Wl1, Wr1, HD, HD, HD, bl1, br1,
                                      xl, xr, HD, HD, NN, 2 * HD, DH, nullptr, nullptr);
    scatter_kernel<<<(TOTE + 255) / 256, 256>>>(ei, fill, srcs);
    attn_kernel<<<attn_blocks, 256>>>(xl, xr, att1, bc1, rowptr, srcs, xin);
    // y = xin @ W1 + b1 (+ fused BN stats)
    bn_zero_kernel<<<1, 256>>>(bnsum, bnsq);
    gemm_f32x2_kernel<<<gN128, 256>>>(xin, xin, HD, HD, HD, W1, W1, DH, DH, DH, b1, b1,
                                      y, y, DH, DH, NN, DH, HD, bnsum, bnsq);
    bn_apply_kernel<<<(NN * DH + 255) / 256, 256>>>(y, bnsum, bnsq, g1, be1, h);

    // ---- Layer 2 ----
    gemm_f32x2_kernel<<<gN768, 256>>>(h, h, DH, DH, DH, Wl2, Wr2, HD, HD, HD, bl2, br2,
                                      xl, xr, HD, HD, NN, 2 * HD, DH, nullptr, nullptr);
    attn_kernel<<<attn_blocks, 256>>>(xl, xr, att2, bc2, rowptr, srcs, h2);
    // y = [h2 | xin] @ W2 + b2   (K=768 concat along A, + fused BN stats)
    bn_zero_kernel<<<1, 256>>>(bnsum, bnsq);
    gemm_f32x2_kernel<<<gN128, 256>>>(h2, xin, HD, HD, HD, W2, W2, DH, DH, DH, b2, b2,
                                      y, y, DH, DH, NN, DH, 2 * HD, bnsum, bnsq);
    bn_apply_kernel<<<(NN * DH + 255) / 256, 256>>>(y, bnsum, bnsq, g2, be2, out);
}

// round 16
// speedup vs baseline: 1.0643x; 1.0643x over previous
#include <cuda_runtime.h>
#include <math.h>
#include <stdint.h>

#define NN 25000
#define EE 400000
#define TOTE (EE + NN)
#define HD 384
#define DH 128

typedef unsigned long long ull;

// ---------------- device scratch ----------------
__device__ __align__(16) float g_xl[NN * HD];
__device__ __align__(16) float g_xr[NN * HD];
__device__ __align__(16) float g_xin[NN * HD];
__device__ __align__(16) float g_h2[NN * HD];
__device__ __align__(16) float g_h[NN * DH];
__device__ __align__(16) float g_y[NN * DH];
__device__ int   g_deg[NN];
__device__ int   g_rowptr[NN + 1];
__device__ int   g_fill[NN];
__device__ int   g_srcs[TOTE];
__device__ float g_bnsum[DH];
__device__ float g_bnsq[DH];

// ---------------- f32x2 helpers ----------------
__device__ __forceinline__ ull dup2(float v) {
    ull d;
    uint32_t u = __float_as_uint(v);
    asm("mov.b64 %0, {%1, %1};" : "=l"(d) : "r"(u));
    return d;
}
__device__ __forceinline__ void unpack2(ull v, float& lo, float& hi) {
    uint32_t a, b;
    asm("mov.b64 {%0, %1}, %2;" : "=r"(a), "=r"(b) : "l"(v));
    lo = __uint_as_float(a);
    hi = __uint_as_float(b);
}
__device__ __forceinline__ void fma2(ull& acc, ull a, ull b) {
    asm("fma.rn.f32x2 %0, %1, %2, %0;" : "+l"(acc) : "l"(a), "l"(b));
}

// ---------------- small helpers ----------------
__device__ __forceinline__ float4 f4add(float4 a, float4 b) {
    return make_float4(a.x + b.x, a.y + b.y, a.z + b.z, a.w + b.w);
}
__device__ __forceinline__ float4 f4scale(float4 a, float s) {
    return make_float4(a.x * s, a.y * s, a.z * s, a.w * s);
}
__device__ __forceinline__ float4 f4fma(float4 a, float s, float4 c) {
    return make_float4(fmaf(a.x, s, c.x), fmaf(a.y, s, c.y),
                       fmaf(a.z, s, c.z), fmaf(a.w, s, c.w));
}
__device__ __forceinline__ float4 f4lrelu(float4 v) {
    const float ns = 0.2f;
    return make_float4(v.x > 0.f ? v.x : ns * v.x,
                       v.y > 0.f ? v.y : ns * v.y,
                       v.z > 0.f ? v.z : ns * v.z,
                       v.w > 0.f ? v.w : ns * v.w);
}
__device__ __forceinline__ float f4dot(float4 a, float4 b) {
    return fmaf(a.x, b.x, fmaf(a.y, b.y, fmaf(a.z, b.z, a.w * b.w)));
}

// ---------------- CSR build ----------------
__global__ void set_int_kernel(int* p, int n, int v) {
    int i = blockIdx.x * blockDim.x + threadIdx.x;
    if (i < n) p[i] = v;
}

__global__ void hist_kernel(const int* __restrict__ ei, int* __restrict__ deg) {
    int i = blockIdx.x * blockDim.x + threadIdx.x;
    if (i < EE) {
        int d = ei[EE + i];
        if (d >= 0 && d < NN) atomicAdd(&deg[d], 1);
    }
}

__global__ void scan_kernel(const int* __restrict__ deg, int* __restrict__ rowptr,
                            int* __restrict__ fill) {
    __shared__ int sh[1024];
    const int CH = 25;
    int t = threadIdx.x;
    int start = t * CH;
    int end = start + CH;
    if (start > NN) start = NN;
    if (end > NN) end = NN;
    int s = 0;
    for (int i = start; i < end; i++) s += deg[i];
    sh[t] = s;
    __syncthreads();
    for (int o = 1; o < 1024; o <<= 1) {
        int v = (t >= o) ? sh[t - o] : 0;
        __syncthreads();
        sh[t] += v;
        __syncthreads();
    }
    int off = (t == 0) ? 0 : sh[t - 1];
    for (int i = start; i < end; i++) {
        rowptr[i] = off;
        fill[i] = off;
        off += deg[i];
    }
    if (t == 1023) rowptr[NN] = sh[1023];
}

__global__ void scatter_kernel(const int* __restrict__ ei, int* __restrict__ fill,
                               int* __restrict__ srcs) {
    int i = blockIdx.x * blockDim.x + threadIdx.x;
    if (i >= TOTE) return;
    int s, d;
    if (i < EE) {
        s = ei[i];
        d = ei[EE + i];
    } else {
        s = d = i - EE;
    }
    if (s < 0 || s >= NN || d < 0 || d >= NN) return;
    int pos = atomicAdd(&fill[d], 1);
    srcs[pos] = s;
}

// ---------------- packed-f32x2 GEMM, double-buffered + swizzled A store ----------------
// (R13 kernel + optional fused BN-stats epilogue)
__global__ void __launch_bounds__(256, 3) gemm_f32x2_kernel(
    const float* __restrict__ A0, const float* __restrict__ A1, int lda0, int lda1,
    int Ksplit, const float* __restrict__ B0, const float* __restrict__ B1, int ldb0,
    int ldb1, int Nsplit, const float* __restrict__ biasA, const float* __restrict__ biasB,
    float* __restrict__ C0, float* __restrict__ C1, int ldc0, int ldc1, int M, int N,
    int K, float* __restrict__ bnsum, float* __restrict__ bnsq) {
    __shared__ float As[2][16][128];
    __shared__ float Bs[2][16][64];

    int tid = threadIdx.x;
    int lane = tid & 31;
    int warp = tid >> 5;
    int ln = lane & 7;
    int lm = lane >> 3;
    int wm = warp >> 1;
    int wn = warp & 1;
    int mb = wm * 32 + lm * 8;
    int nb = wn * 32 + ln * 4;
    int bm = blockIdx.y * 128;
    int bn = blockIdx.x * 64;

    int ar = tid >> 2;
    int akq = (tid & 3) << 2;
    int sw = (akq >> 2) << 3;
    int arx = ar ^ sw;
    int br = tid >> 4;
    int bnc = (tid & 15) << 2;
    int agrow0 = bm + ar;
    int agrow1 = bm + ar + 64;
    int bcol = bn + bnc;

    ull acc[8][2];
#pragma unroll
    for (int i = 0; i < 8; i++) {
        acc[i][0] = 0ull;
        acc[i][1] = 0ull;
    }

    int nchunks = K >> 4;

    float4 va0, va1, vb;
    {
        int kg = akq;
        va0 = make_float4(0.f, 0.f, 0.f, 0.f);
        va1 = va0;
        if (agrow0 < M)
            va0 = (kg < Ksplit) ? *(const float4*)(A0 + (size_t)agrow0 * lda0 + kg)
                                : *(const float4*)(A1 + (size_t)agrow0 * lda1 + (kg - Ksplit));
        if (agrow1 < M)
            va1 = (kg < Ksplit) ? *(const float4*)(A0 + (size_t)agrow1 * lda0 + kg)
                                : *(const float4*)(A1 + (size_t)agrow1 * lda1 + (kg - Ksplit));
        int kgb = br;
        vb = (bcol < Nsplit) ? *(const float4*)(B0 + (size_t)kgb * ldb0 + bcol)
                             : *(const float4*)(B1 + (size_t)kgb * ldb1 + (bcol - Nsplit));
    }
    As[0][akq + 0][arx] = va0.x;
    As[0][akq + 1][arx] = va0.y;
    As[0][akq + 2][arx] = va0.z;
    As[0][akq + 3][arx] = va0.w;
    As[0][akq + 0][arx + 64] = va1.x;
    As[0][akq + 1][arx + 64] = va1.y;
    As[0][akq + 2][arx + 64] = va1.z;
    As[0][akq + 3][arx + 64] = va1.w;
    *(float4*)&Bs[0][br][bnc] = vb;
    __syncthreads();

    for (int kc = 0; kc < nchunks; kc++) {
        int p = kc & 1;
        bool more = (kc + 1) < nchunks;
        if (more) {
            int kg = (kc + 1) * 16 + akq;
            va0 = make_float4(0.f, 0.f, 0.f, 0.f);
            va1 = va0;
            if (agrow0 < M)
                va0 = (kg < Ksplit)
                          ? *(const float4*)(A0 + (size_t)agrow0 * lda0 + kg)
                          : *(const float4*)(A1 + (size_t)agrow0 * lda1 + (kg - Ksplit));
            if (agrow1 < M)
                va1 = (kg < Ksplit)
                          ? *(const float4*)(A0 + (size_t)agrow1 * lda0 + kg)
                          : *(const float4*)(A1 + (size_t)agrow1 * lda1 + (kg - Ksplit));
            int kgb = (kc + 1) * 16 + br;
            vb = (bcol < Nsplit)
                     ? *(const float4*)(B0 + (size_t)kgb * ldb0 + bcol)
                     : *(const float4*)(B1 + (size_t)kgb * ldb1 + (bcol - Nsplit));
        }
#pragma unroll
        for (int kk = 0; kk < 16; kk++) {
            int g = (kk >> 2) << 3;
            int mbx = mb ^ g;
            float4 av0 = *(const float4*)&As[p][kk][mbx];
            float4 av1 = *(const float4*)&As[p][kk][mbx + 4];
            ulonglong2 bq = *(const ulonglong2*)&Bs[p][kk][nb];
            ull ad[8] = {dup2(av0.x), dup2(av0.y), dup2(av0.z), dup2(av0.w),
                         dup2(av1.x), dup2(av1.y), dup2(av1.z), dup2(av1.w)};
#pragma unroll
            for (int i = 0; i < 8; i++) {
                fma2(acc[i][0], ad[i], bq.x);
                fma2(acc[i][1], ad[i], bq.y);
            }
        }
        if (more) {
            int q = p ^ 1;
            As[q][akq + 0][arx] = va0.x;
            As[q][akq + 1][arx] = va0.y;
            As[q][akq + 2][arx] = va0.z;
            As[q][akq + 3][arx] = va0.w;
            As[q][akq + 0][arx + 64] = va1.x;
            As[q][akq + 1][arx + 64] = va1.y;
            As[q][akq + 2][arx + 64] = va1.z;
            As[q][akq + 3][arx + 64] = va1.w;
            *(float4*)&Bs[q][br][bnc] = vb;
            __syncthreads();
        }
    }

    int colg = bn + nb;
    bool side1 = colg >= Nsplit;
    int col = side1 ? colg - Nsplit : colg;
    float* __restrict__ Cp = side1 ? C1 : C0;
    int ldc = side1 ? ldc1 : ldc0;
    const float* __restrict__ bp = side1 ? biasB : biasA;
    float b0 = bp[col], b1v = bp[col + 1], b2v = bp[col + 2], b3v = bp[col + 3];
    float cs0 = 0.f, cs1 = 0.f, cs2 = 0.f, cs3 = 0.f;
    float cq0 = 0.f, cq1 = 0.f, cq2 = 0.f, cq3 = 0.f;
#pragma unroll
    for (int i = 0; i < 8; i++) {
        int row = bm + mb + i;
        if (row >= M) continue;
        float v0, v1, v2, v3;
        unpack2(acc[i][0], v0, v1);
        unpack2(acc[i][1], v2, v3);
        v0 += b0; v1 += b1v; v2 += b2v; v3 += b3v;
        *(float4*)(Cp + (size_t)row * ldc + col) = make_float4(v0, v1, v2, v3);
        cs0 += v0; cs1 += v1; cs2 += v2; cs3 += v3;
        cq0 = fmaf(v0, v0, cq0);
        cq1 = fmaf(v1, v1, cq1);
        cq2 = fmaf(v2, v2, cq2);
        cq3 = fmaf(v3, v3, cq3);
    }

    if (bnsum) {
        __syncthreads();
        float* sred = &As[0][0][0];
        if (tid < 128) sred[tid] = 0.f;
        __syncthreads();
        atomicAdd(&sred[nb + 0], cs0);
        atomicAdd(&sred[nb + 1], cs1);
        atomicAdd(&sred[nb + 2], cs2);
        atomicAdd(&sred[nb + 3], cs3);
        atomicAdd(&sred[64 + nb + 0], cq0);
        atomicAdd(&sred[64 + nb + 1], cq1);
        atomicAdd(&sred[64 + nb + 2], cq2);
        atomicAdd(&sred[64 + nb + 3], cq3);
        __syncthreads();
        if (tid < 64) {
            atomicAdd(&bnsum[bn + tid], sred[tid]);
            atomicAdd(&bnsq[bn + tid], sred[64 + tid]);
        }
    }
}

// ---------------- GATv2 attention: one warp per dst node, online softmax ----------------
// (R13 version — no prefetch; R15 showed prefetch costs ~+20us/layer)
__global__ void attn_kernel(const float* __restrict__ xl, const float* __restrict__ xr,
                            const float* __restrict__ att, const float* __restrict__ bias,
                            const int* __restrict__ rowptr, const int* __restrict__ srcs,
                            float* __restrict__ out) {
    int w = (blockIdx.x * blockDim.x + threadIdx.x) >> 5;
    if (w >= NN) return;
    int lane = threadIdx.x & 31;
    const float4* xl4 = (const float4*)xl;
    const float4* xr4 = (const float4*)xr;
    const float4* at4 = (const float4*)att;
    const float4* b4 = (const float4*)bias;

    size_t rb = (size_t)w * 96 + lane;
    float4 r0 = xr4[rb], r1 = xr4[rb + 32], r2 = xr4[rb + 64];
    float4 a0 = at4[lane], a1 = at4[32 + lane], a2 = at4[64 + lane];

    float4 acc0 = make_float4(0, 0, 0, 0), acc1 = acc0, acc2 = acc0;
    float den0 = 0.f, den1 = 0.f, den2 = 0.f;
    float m0 = -1e30f, m1 = -1e30f, m2 = -1e30f;

    int beg = rowptr[w], end = rowptr[w + 1];
    for (int e = beg; e < end; e++) {
        int s = srcs[e];
        const float4* p = xl4 + (size_t)s * 96 + lane;
        float4 x0 = p[0], x1 = p[32], x2 = p[64];
        float s0 = f4dot(a0, f4lrelu(f4add(x0, r0)));
        float s1 = f4dot(a1, f4lrelu(f4add(x1, r1)));
        float s2 = f4dot(a2, f4lrelu(f4add(x2, r2)));
#pragma unroll
        for (int o = 16; o; o >>= 1) {
            s0 += __shfl_xor_sync(0xffffffffu, s0, o);
            s1 += __shfl_xor_sync(0xffffffffu, s1, o);
            s2 += __shfl_xor_sync(0xffffffffu, s2, o);
        }
        if (s0 > m0) { float cc = __expf(m0 - s0); acc0 = f4scale(acc0, cc); den0 *= cc; m0 = s0; }
        if (s1 > m1) { float cc = __expf(m1 - s1); acc1 = f4scale(acc1, cc); den1 *= cc; m1 = s1; }
        if (s2 > m2) { float cc = __expf(m2 - s2); acc2 = f4scale(acc2, cc); den2 *= cc; m2 = s2; }
        float w0 = __expf(s0 - m0);
        float w1 = __expf(s1 - m1);
        float w2 = __expf(s2 - m2);
        acc0 = f4fma(x0, w0, acc0); den0 += w0;
        acc1 = f4fma(x1, w1, acc1); den1 += w1;
        acc2 = f4fma(x2, w2, acc2); den2 += w2;
    }
    float4* o4 = (float4*)out;
    o4[rb]      = f4add(f4scale(acc0, 1.0f / den0), b4[lane]);
    o4[rb + 32] = f4add(f4scale(acc1, 1.0f / den1), b4[32 + lane]);
    o4[rb + 64] = f4add(f4scale(acc2, 1.0f / den2), b4[64 + lane]);
}

// ---------------- BatchNorm ----------------
__global__ void bn_zero_kernel(float* s, float* q) {
    int i = threadIdx.x;
    if (i < DH) s[i] = 0.f;
    else if (i < 2 * DH) q[i - DH] = 0.f;
}

__global__ void bn_apply_kernel(const float* __restrict__ x, const float* __restrict__ sum,
                                const float* __restrict__ sq, const float* __restrict__ g,
                                const float* __restrict__ be, float* __restrict__ out) {
    int i = blockIdx.x * blockDim.x + threadIdx.x;
    if (i >= NN * DH) return;
    int col = i & (DH - 1);
    const float invN = 1.0f / (float)NN;
    float mu = sum[col] * invN;
    float var = sq[col] * invN - mu * mu;
    float v = g[col] * (x[i] - mu) * rsqrtf(var + 1e-5f) + be[col];
    out[i] = v > 0.f ? v : 0.f;
}

// ---------------- host ----------------
static void* symaddr(const void* sym) {
    void* p = nullptr;
    cudaGetSymbolAddress(&p, sym);
    return p;
}

extern "C" void kernel_launch(void* const* d_in, const int* in_sizes, int n_in,
                              void* d_out, int out_size) {
    const float* x       = (const float*)d_in[0];
    const int* ei        = (const int*)d_in[1];
    const float* Wl1 = (const float*)d_in[2];
    const float* bl1 = (const float*)d_in[3];
    const float* Wr1 = (const float*)d_in[4];
    const float* br1 = (const float*)d_in[5];
    const float* att1 = (const float*)d_in[6];
    const float* bc1 = (const float*)d_in[7];
    const float* g1 = (const float*)d_in[8];
    const float* be1 = (const float*)d_in[9];
    const float* Wl2 = (const float*)d_in[10];
    const float* bl2 = (const float*)d_in[11];
    const float* Wr2 = (const float*)d_in[12];
    const float* br2 = (const float*)d_in[13];
    const float* att2 = (const float*)d_in[14];
    const float* bc2 = (const float*)d_in[15];
    const float* g2 = (const float*)d_in[16];
    const float* be2 = (const float*)d_in[17];
    const float* W1 = (const float*)d_in[18];
    const float* b1 = (const float*)d_in[19];
    const float* W2 = (const float*)d_in[20];
    const float* b2 = (const float*)d_in[21];
    float* out = (float*)d_out;

    float* xl    = (float*)symaddr(g_xl);
    float* xr    = (float*)symaddr(g_xr);
    float* xin   = (float*)symaddr(g_xin);
    float* h2    = (float*)symaddr(g_h2);
    float* h     = (float*)symaddr(g_h);
    float* y     = (float*)symaddr(g_y);
    int* deg     = (int*)symaddr(g_deg);
    int* rowptr  = (int*)symaddr(g_rowptr);
    int* fill    = (int*)symaddr(g_fill);
    int* srcs    = (int*)symaddr(g_srcs);
    float* bnsum = (float*)symaddr(g_bnsum);
    float* bnsq  = (float*)symaddr(g_bnsq);

    const int MT = (NN + 127) / 128;  // 196
    dim3 gN768(2 * HD / 64, MT);      // 12 x 196
    dim3 gN128(DH / 64, MT);          // 2 x 196
    int attn_blocks = (NN * 32 + 255) / 256;

    // CSR part 1 (3 launches so the big fused GEMM sits in the profiled slot)
    set_int_kernel<<<(NN + 255) / 256, 256>>>(deg, NN, 1);
    hist_kernel<<<(EE + 255) / 256, 256>>>(ei, deg);
    scan_kernel<<<1, 1024>>>(deg, rowptr, fill);

    // ---- Layer 1: [xl | xr] = x @ [Wl1 | Wr1] + [bl1 | br1] ----
    gemm_f32x2_kernel<<<gN768, 256>>>(x, x, DH, DH, DH, Wl1, Wr1, HD, HD, HD, bl1, br1,
                                      xl, xr, HD, HD, NN, 2 * HD, DH, nullptr, nullptr);
    scatter_kernel<<<(TOTE + 255) / 256, 256>>>(ei, fill, srcs);
    attn_kernel<<<attn_blocks, 256>>>(xl, xr, att1, bc1, rowptr, srcs, xin);
    // y = xin @ W1 + b1 (+ fused BN stats)
    bn_zero_kernel<<<1, 256>>>(bnsum, bnsq);
    gemm_f32x2_kernel<<<gN128, 256>>>(xin, xin, HD, HD, HD, W1, W1, DH, DH, DH, b1, b1,
                                      y, y, DH, DH, NN, DH, HD, bnsum, bnsq);
    bn_apply_kernel<<<(NN * DH + 255) / 256, 256>>>(y, bnsum, bnsq, g1, be1, h);

    // ---- Layer 2 ----
    gemm_f32x2_kernel<<<gN768, 256>>>(h, h, DH, DH, DH, Wl2, Wr2, HD, HD, HD, bl2, br2,
                                      xl, xr, HD, HD, NN, 2 * HD, DH, nullptr, nullptr);
    attn_kernel<<<attn_blocks, 256>>>(xl, xr, att2, bc2, rowptr, srcs, h2);
    // y = [h2 | xin] @ W2 + b2   (K=768 concat along A, + fused BN stats)
    bn_zero_kernel<<<1, 256>>>(bnsum, bnsq);
    gemm_f32x2_kernel<<<gN128, 256>>>(h2, xin, HD, HD, HD, W2, W2, DH, DH, DH, b2, b2,
                                      y, y, DH, DH, NN, DH, 2 * HD, bnsum, bnsq);
    bn_apply_kernel<<<(NN * DH + 255) / 256, 256>>>(y, bnsum, bnsq, g2, be2, out);
}